// round 1
// baseline (speedup 1.0000x reference)
#include <cuda_runtime.h>
#include <cuda_bf16.h>
#include <cstdint>

// Problem shape (fixed for this dataset entry)
#define S_TOK 2048
#define K_DIM 4096
#define O_DIM 4096
#define NGRP  32
#define GS    128

#define BM 128
#define BN 128
#define PADS 136   // padded bf16 row stride for smem tiles (conflict avoidance)

// Scratch (device globals — no runtime allocation allowed)
__device__ __nv_bfloat16 g_xq[(size_t)S_TOK * K_DIM]; // centered, quantized activations (exact ints in bf16)
__device__ float g_xscale[S_TOK];

// ---------------------------------------------------------------------------
// Kernel 1: per-token asymmetric quantization of activations
// ---------------------------------------------------------------------------
__global__ __launch_bounds__(256) void quant_act_kernel(const float* __restrict__ x) {
    const int row = blockIdx.x;
    const int tid = threadIdx.x;
    const float* xr = x + (size_t)row * K_DIM;

    float4 v[4];
    float mn = INFINITY, mx = -INFINITY;
#pragma unroll
    for (int i = 0; i < 4; i++) {
        v[i] = ((const float4*)xr)[tid + i * 256];
        mn = fminf(mn, fminf(fminf(v[i].x, v[i].y), fminf(v[i].z, v[i].w)));
        mx = fmaxf(mx, fmaxf(fmaxf(v[i].x, v[i].y), fmaxf(v[i].z, v[i].w)));
    }
#pragma unroll
    for (int o = 16; o; o >>= 1) {
        mn = fminf(mn, __shfl_xor_sync(0xffffffffu, mn, o));
        mx = fmaxf(mx, __shfl_xor_sync(0xffffffffu, mx, o));
    }
    __shared__ float smn[8], smx[8];
    __shared__ float s_scale, s_zp;
    const int wid = tid >> 5, lane = tid & 31;
    if (lane == 0) { smn[wid] = mn; smx[wid] = mx; }
    __syncthreads();
    if (tid == 0) {
        float a = smn[0], b = smx[0];
#pragma unroll
        for (int i = 1; i < 8; i++) { a = fminf(a, smn[i]); b = fmaxf(b, smx[i]); }
        float sc = fmaxf((b - a) * (1.0f / 255.0f), 1e-5f);
        float zp = fminf(fmaxf(rintf(-a / sc), 0.0f), 255.0f);
        s_scale = sc; s_zp = zp;
        g_xscale[row] = sc;
    }
    __syncthreads();
    const float sc = s_scale, zp = s_zp;

    __nv_bfloat16* outp = g_xq + (size_t)row * K_DIM;
#pragma unroll
    for (int i = 0; i < 4; i++) {
        float q0 = fminf(fmaxf(rintf(v[i].x / sc) + zp, 0.0f), 255.0f) - zp;
        float q1 = fminf(fmaxf(rintf(v[i].y / sc) + zp, 0.0f), 255.0f) - zp;
        float q2 = fminf(fmaxf(rintf(v[i].z / sc) + zp, 0.0f), 255.0f) - zp;
        float q3 = fminf(fmaxf(rintf(v[i].w / sc) + zp, 0.0f), 255.0f) - zp;
        __nv_bfloat162 p0, p1;
        p0.x = __float2bfloat16_rn(q0); p0.y = __float2bfloat16_rn(q1);
        p1.x = __float2bfloat16_rn(q2); p1.y = __float2bfloat16_rn(q3);
        ((__nv_bfloat162*)outp)[(tid + i * 256) * 2 + 0] = p0;
        ((__nv_bfloat162*)outp)[(tid + i * 256) * 2 + 1] = p1;
    }
}

// ---------------------------------------------------------------------------
// Kernel 2: grouped-dequant bf16 GEMM with per-group rescale (mma.sync)
// ---------------------------------------------------------------------------
#define MMA16816(d, a, b)                                                          \
    asm volatile(                                                                  \
        "mma.sync.aligned.m16n8k16.row.col.f32.bf16.bf16.f32 "                     \
        "{%0,%1,%2,%3},{%4,%5,%6,%7},{%8,%9},{%0,%1,%2,%3};"                       \
        : "+f"(d[0]), "+f"(d[1]), "+f"(d[2]), "+f"(d[3])                           \
        : "r"(a[0]), "r"(a[1]), "r"(a[2]), "r"(a[3]), "r"(b[0]), "r"(b[1]))

extern __shared__ char smem_raw[];

__global__ __launch_bounds__(256, 1) void gemm_w4a8_kernel(
    const int* __restrict__ qweight,      // [O, NGRP, GS] int32 codes
    const float* __restrict__ w_scales,   // [O, NGRP]
    const int* __restrict__ w_zp,         // [O, NGRP]
    const float* __restrict__ bias,       // [O]
    float* __restrict__ out)              // [S, O]
{
    __nv_bfloat16* As = (__nv_bfloat16*)smem_raw;              // [BM][PADS]
    __nv_bfloat16* Ws = As + BM * PADS;                        // [BN][PADS]
    float* Ssc = (float*)(Ws + BN * PADS);                     // [BN]

    const int tid = threadIdx.x;
    const int warp = tid >> 5, lane = tid & 31;
    const int warp_m = warp & 1;       // 2 warps along M
    const int warp_n = warp >> 1;      // 4 warps along N
    const int bm = (blockIdx.x % (S_TOK / BM)) * BM;  // m fastest -> L2 reuse of weights
    const int bn = (blockIdx.x / (S_TOK / BM)) * BN;

    float facc[4][4][4];
    float gacc[4][4][4];
#pragma unroll
    for (int i = 0; i < 4; i++)
#pragma unroll
        for (int j = 0; j < 4; j++)
#pragma unroll
            for (int k = 0; k < 4; k++) { facc[i][j][k] = 0.f; gacc[i][j][k] = 0.f; }

    const int ldrow = tid >> 1;            // 0..127
    const int ldcol = (tid & 1) * 64;      // half-row

    for (int g = 0; g < NGRP; ++g) {
        // --- load A tile (bf16, already centered) ---
        {
            const int4* src = (const int4*)(g_xq + (size_t)(bm + ldrow) * K_DIM + g * GS + ldcol);
            int4* dst = (int4*)(As + ldrow * PADS + ldcol);
#pragma unroll
            for (int i = 0; i < 8; i++) dst[i] = src[i];
        }
        // --- load + dequant W tile (int32 codes -> centered bf16) ---
        {
            const float zpf = (float)w_zp[(size_t)(bn + ldrow) * NGRP + g];
            const int4* src = (const int4*)(qweight + (size_t)(bn + ldrow) * K_DIM + g * GS + ldcol);
            __nv_bfloat16* dst = Ws + ldrow * PADS + ldcol;
#pragma unroll
            for (int i = 0; i < 16; i++) {
                int4 c = src[i];
                __nv_bfloat162 p0, p1;
                p0.x = __float2bfloat16_rn((float)c.x - zpf);
                p0.y = __float2bfloat16_rn((float)c.y - zpf);
                p1.x = __float2bfloat16_rn((float)c.z - zpf);
                p1.y = __float2bfloat16_rn((float)c.w - zpf);
                *(__nv_bfloat162*)(dst + i * 4 + 0) = p0;
                *(__nv_bfloat162*)(dst + i * 4 + 2) = p1;
            }
        }
        if (tid < BN) Ssc[tid] = w_scales[(size_t)(bn + tid) * NGRP + g];
        __syncthreads();

        // --- 8 k-steps of m16n8k16 ---
#pragma unroll
        for (int ks = 0; ks < 8; ks++) {
            uint32_t afrag[4][4], bfrag[4][2];
            const int a_mrow = warp_m * 64 + (lane & 15);
            const int a_kcol = ks * 16 + (lane >> 4) * 8;
#pragma unroll
            for (int mi = 0; mi < 4; mi++) {
                uint32_t addr = (uint32_t)__cvta_generic_to_shared(
                    As + (a_mrow + mi * 16) * PADS + a_kcol);
                asm volatile("ldmatrix.sync.aligned.m8n8.x4.shared.b16 {%0,%1,%2,%3},[%4];"
                             : "=r"(afrag[mi][0]), "=r"(afrag[mi][1]),
                               "=r"(afrag[mi][2]), "=r"(afrag[mi][3])
                             : "r"(addr));
            }
            const int b_nrow = warp_n * 32 + (lane & 7);
            const int b_kcol = ks * 16 + ((lane >> 3) & 1) * 8;
#pragma unroll
            for (int ni = 0; ni < 4; ni++) {
                uint32_t addr = (uint32_t)__cvta_generic_to_shared(
                    Ws + (b_nrow + ni * 8) * PADS + b_kcol);
                asm volatile("ldmatrix.sync.aligned.m8n8.x2.shared.b16 {%0,%1},[%2];"
                             : "=r"(bfrag[ni][0]), "=r"(bfrag[ni][1])
                             : "r"(addr));
            }
#pragma unroll
            for (int mi = 0; mi < 4; mi++)
#pragma unroll
                for (int ni = 0; ni < 4; ni++) MMA16816(gacc[mi][ni], afrag[mi], bfrag[ni]);
        }

        // --- per-group rescale into final accumulator (reads Ssc before it changes) ---
#pragma unroll
        for (int ni = 0; ni < 4; ni++) {
            const int cb = warp_n * 32 + ni * 8 + (lane & 3) * 2;
            const float s0 = Ssc[cb], s1 = Ssc[cb + 1];
#pragma unroll
            for (int mi = 0; mi < 4; mi++) {
                facc[mi][ni][0] += gacc[mi][ni][0] * s0;
                facc[mi][ni][1] += gacc[mi][ni][1] * s1;
                facc[mi][ni][2] += gacc[mi][ni][2] * s0;
                facc[mi][ni][3] += gacc[mi][ni][3] * s1;
                gacc[mi][ni][0] = 0.f; gacc[mi][ni][1] = 0.f;
                gacc[mi][ni][2] = 0.f; gacc[mi][ni][3] = 0.f;
            }
        }
        __syncthreads();  // before smem tiles are overwritten next group
    }

    // --- epilogue: out = facc * x_scale[row] + bias[col] ---
#pragma unroll
    for (int mi = 0; mi < 4; mi++) {
        const int row0 = bm + warp_m * 64 + mi * 16 + (lane >> 2);
        const int row1 = row0 + 8;
        const float xs0 = g_xscale[row0];
        const float xs1 = g_xscale[row1];
#pragma unroll
        for (int ni = 0; ni < 4; ni++) {
            const int col = bn + warp_n * 32 + ni * 8 + (lane & 3) * 2;
            const float2 bv = *(const float2*)(bias + col);
            float2 o0, o1;
            o0.x = facc[mi][ni][0] * xs0 + bv.x;
            o0.y = facc[mi][ni][1] * xs0 + bv.y;
            o1.x = facc[mi][ni][2] * xs1 + bv.x;
            o1.y = facc[mi][ni][3] * xs1 + bv.y;
            *(float2*)(out + (size_t)row0 * O_DIM + col) = o0;
            *(float2*)(out + (size_t)row1 * O_DIM + col) = o1;
        }
    }
}

// ---------------------------------------------------------------------------
extern "C" void kernel_launch(void* const* d_in, const int* in_sizes, int n_in,
                              void* d_out, int out_size) {
    const float* x        = (const float*)d_in[0];
    const int*   qweight  = (const int*)d_in[1];
    const float* w_scales = (const float*)d_in[2];
    const int*   w_zp     = (const int*)d_in[3];
    const float* bias     = (const float*)d_in[4];
    float*       out      = (float*)d_out;

    quant_act_kernel<<<S_TOK, 256>>>(x);

    const int smem_bytes = (BM * PADS + BN * PADS) * (int)sizeof(__nv_bfloat16)
                         + BN * (int)sizeof(float);
    cudaFuncSetAttribute(gemm_w4a8_kernel,
                         cudaFuncAttributeMaxDynamicSharedMemorySize, smem_bytes);
    const int grid = (S_TOK / BM) * (O_DIM / BN);
    gemm_w4a8_kernel<<<grid, 256, smem_bytes>>>(qweight, w_scales, w_zp, bias, out);
}

// round 2
// speedup vs baseline: 1.6328x; 1.6328x over previous
#include <cuda_runtime.h>
#include <cuda_fp16.h>
#include <cstdint>

// Problem shape (fixed)
#define S_TOK 2048
#define K_DIM 4096
#define O_DIM 4096
#define NGRP  32
#define GS    128

#define BM 128
#define BN 128
#define BK 128
#define THREADS 256

// Device-global scratch (no runtime allocation allowed)
__device__ __half g_xq[(size_t)S_TOK * K_DIM];   // centered quantized activations (exact ints in fp16)
__device__ float  g_xscale[S_TOK];
__device__ __half g_wq[(size_t)O_DIM * K_DIM];   // fully dequantized weights (code-zp)*scale in fp16

// ---------------------------------------------------------------------------
// Kernel 1: per-token asymmetric activation quantization -> centered fp16
// ---------------------------------------------------------------------------
__global__ __launch_bounds__(256) void quant_act_kernel(const float* __restrict__ x) {
    const int row = blockIdx.x;
    const int tid = threadIdx.x;
    const float* xr = x + (size_t)row * K_DIM;

    float4 v[4];
    float mn = INFINITY, mx = -INFINITY;
#pragma unroll
    for (int i = 0; i < 4; i++) {
        v[i] = ((const float4*)xr)[tid + i * 256];
        mn = fminf(mn, fminf(fminf(v[i].x, v[i].y), fminf(v[i].z, v[i].w)));
        mx = fmaxf(mx, fmaxf(fmaxf(v[i].x, v[i].y), fmaxf(v[i].z, v[i].w)));
    }
#pragma unroll
    for (int o = 16; o; o >>= 1) {
        mn = fminf(mn, __shfl_xor_sync(0xffffffffu, mn, o));
        mx = fmaxf(mx, __shfl_xor_sync(0xffffffffu, mx, o));
    }
    __shared__ float smn[8], smx[8];
    __shared__ float s_scale, s_zp;
    const int wid = tid >> 5, lane = tid & 31;
    if (lane == 0) { smn[wid] = mn; smx[wid] = mx; }
    __syncthreads();
    if (tid == 0) {
        float a = smn[0], b = smx[0];
#pragma unroll
        for (int i = 1; i < 8; i++) { a = fminf(a, smn[i]); b = fmaxf(b, smx[i]); }
        float sc = fmaxf((b - a) * (1.0f / 255.0f), 1e-5f);
        float zp = fminf(fmaxf(rintf(-a / sc), 0.0f), 255.0f);
        s_scale = sc; s_zp = zp;
        g_xscale[row] = sc;
    }
    __syncthreads();
    const float sc = s_scale, zp = s_zp;

    __half* outp = g_xq + (size_t)row * K_DIM;
#pragma unroll
    for (int i = 0; i < 4; i++) {
        float q0 = fminf(fmaxf(rintf(v[i].x / sc) + zp, 0.0f), 255.0f) - zp;
        float q1 = fminf(fmaxf(rintf(v[i].y / sc) + zp, 0.0f), 255.0f) - zp;
        float q2 = fminf(fmaxf(rintf(v[i].z / sc) + zp, 0.0f), 255.0f) - zp;
        float q3 = fminf(fmaxf(rintf(v[i].w / sc) + zp, 0.0f), 255.0f) - zp;
        __half2 p0, p1;
        p0.x = __float2half_rn(q0); p0.y = __float2half_rn(q1);
        p1.x = __float2half_rn(q2); p1.y = __float2half_rn(q3);
        ((__half2*)outp)[(tid + i * 256) * 2 + 0] = p0;
        ((__half2*)outp)[(tid + i * 256) * 2 + 1] = p1;
    }
}

// ---------------------------------------------------------------------------
// Kernel 2: full weight dequant int32 codes -> fp16 (code - zp) * scale
// ---------------------------------------------------------------------------
__global__ __launch_bounds__(256) void dequant_w_kernel(
    const int* __restrict__ qw, const float* __restrict__ wsc, const int* __restrict__ wzp)
{
    const int o = blockIdx.x;
    const int t = threadIdx.x;
    const int g = t >> 3;                       // 16 codes per thread, within one group
    const float s = wsc[o * NGRP + g];
    const float z = (float)wzp[o * NGRP + g];
    const int4* src = (const int4*)(qw + (size_t)o * K_DIM + t * 16);
    __half2 h[8];
#pragma unroll
    for (int j = 0; j < 4; j++) {
        int4 c = src[j];
        h[j * 2 + 0].x = __float2half_rn(((float)c.x - z) * s);
        h[j * 2 + 0].y = __float2half_rn(((float)c.y - z) * s);
        h[j * 2 + 1].x = __float2half_rn(((float)c.z - z) * s);
        h[j * 2 + 1].y = __float2half_rn(((float)c.w - z) * s);
    }
    uint4* dst = (uint4*)(g_wq + (size_t)o * K_DIM + t * 16);
    dst[0] = *(uint4*)&h[0];
    dst[1] = *(uint4*)&h[4];
}

// ---------------------------------------------------------------------------
// Kernel 3: dense fp16 GEMM, cp.async double-buffered, mma.sync.m16n8k16
// ---------------------------------------------------------------------------
#define MMA16816(d, a, b)                                                          \
    asm volatile(                                                                  \
        "mma.sync.aligned.m16n8k16.row.col.f32.f16.f16.f32 "                       \
        "{%0,%1,%2,%3},{%4,%5,%6,%7},{%8,%9},{%0,%1,%2,%3};"                       \
        : "+f"(d[0]), "+f"(d[1]), "+f"(d[2]), "+f"(d[3])                           \
        : "r"(a[0]), "r"(a[1]), "r"(a[2]), "r"(a[3]), "r"(b[0]), "r"(b[1]))

__device__ __forceinline__ uint32_t sw_off(int row, int c) {
    // tile row stride 256B (128 fp16); XOR-8 swizzle on 16B chunks within 128B halves
    return (uint32_t)(row * 256 + ((c >> 3) << 7) + ((((c & 7) ^ (row & 7))) << 4));
}

__device__ __forceinline__ void cp_async16(uint32_t smem_addr, const void* gptr) {
    asm volatile("cp.async.cg.shared.global [%0], [%1], 16;\n" :: "r"(smem_addr), "l"(gptr));
}
#define CP_COMMIT() asm volatile("cp.async.commit_group;\n")
#define CP_WAIT0()  asm volatile("cp.async.wait_group 0;\n")

#define STAGE_BYTES 65536   // A 32KB + B 32KB

extern __shared__ char smem_raw[];

__global__ __launch_bounds__(THREADS, 1) void gemm_f16_kernel(
    const float* __restrict__ bias, float* __restrict__ out)
{
    const int tid  = threadIdx.x;
    const int warp = tid >> 5, lane = tid & 31;
    const int warp_m = warp & 1;   // 2 warps along M (64 rows each)
    const int warp_n = warp >> 1;  // 4 warps along N (32 cols each)
    const int bm = (blockIdx.x % (S_TOK / BM)) * BM;   // m fastest for weight L2 reuse
    const int bn = (blockIdx.x / (S_TOK / BM)) * BN;

    const uint32_t sbase = (uint32_t)__cvta_generic_to_shared(smem_raw);

    // loader mapping: thread t -> row t/2, chunks (t&1)*8 .. +7 (each chunk = 16B = 8 fp16)
    const int ldrow = tid >> 1;
    const int ldc0  = (tid & 1) * 8;
    const __half* gA = g_xq + (size_t)(bm + ldrow) * K_DIM + ldc0 * 8;
    const __half* gB = g_wq + (size_t)(bn + ldrow) * K_DIM + ldc0 * 8;

    auto load_stage = [&](int s, int kt) {
        const uint32_t a_s = sbase + s * STAGE_BYTES;
        const uint32_t b_s = a_s + 32768;
#pragma unroll
        for (int i = 0; i < 8; i++) {
            const int c = ldc0 + i;
            cp_async16(a_s + sw_off(ldrow, c), gA + kt * BK + i * 8);
            cp_async16(b_s + sw_off(ldrow, c), gB + kt * BK + i * 8);
        }
    };

    float facc[4][4][4];
#pragma unroll
    for (int i = 0; i < 4; i++)
#pragma unroll
        for (int j = 0; j < 4; j++)
#pragma unroll
            for (int k = 0; k < 4; k++) facc[i][j][k] = 0.f;

    load_stage(0, 0);
    CP_COMMIT();

    const int NKT = K_DIM / BK;   // 32
    for (int kt = 0; kt < NKT; kt++) {
        CP_WAIT0();
        __syncthreads();
        if (kt + 1 < NKT) { load_stage((kt + 1) & 1, kt + 1); CP_COMMIT(); }

        const uint32_t a_s = sbase + (kt & 1) * STAGE_BYTES;
        const uint32_t b_s = a_s + 32768;

#pragma unroll
        for (int ks = 0; ks < 8; ks++) {
            uint32_t afrag[4][4], bfrag[4][2];
            const int arow = warp_m * 64 + (lane & 15);
            const int ac   = ks * 2 + (lane >> 4);
#pragma unroll
            for (int mi = 0; mi < 4; mi++) {
                uint32_t addr = a_s + sw_off(arow + mi * 16, ac);
                asm volatile("ldmatrix.sync.aligned.m8n8.x4.shared.b16 {%0,%1,%2,%3},[%4];"
                             : "=r"(afrag[mi][0]), "=r"(afrag[mi][1]),
                               "=r"(afrag[mi][2]), "=r"(afrag[mi][3])
                             : "r"(addr));
            }
            const int brow = warp_n * 32 + (lane & 7);
            const int bc   = ks * 2 + ((lane >> 3) & 1);
#pragma unroll
            for (int ni = 0; ni < 4; ni++) {
                uint32_t addr = b_s + sw_off(brow + ni * 8, bc);
                asm volatile("ldmatrix.sync.aligned.m8n8.x2.shared.b16 {%0,%1},[%2];"
                             : "=r"(bfrag[ni][0]), "=r"(bfrag[ni][1])
                             : "r"(addr));
            }
#pragma unroll
            for (int mi = 0; mi < 4; mi++)
#pragma unroll
                for (int ni = 0; ni < 4; ni++) MMA16816(facc[mi][ni], afrag[mi], bfrag[ni]);
        }
        __syncthreads();   // protect current stage until all warps done (next iter overwrites it)
    }

    // epilogue: out = facc * x_scale[row] + bias[col]
#pragma unroll
    for (int mi = 0; mi < 4; mi++) {
        const int row0 = bm + warp_m * 64 + mi * 16 + (lane >> 2);
        const int row1 = row0 + 8;
        const float xs0 = g_xscale[row0];
        const float xs1 = g_xscale[row1];
#pragma unroll
        for (int ni = 0; ni < 4; ni++) {
            const int col = bn + warp_n * 32 + ni * 8 + (lane & 3) * 2;
            const float2 bv = *(const float2*)(bias + col);
            float2 o0, o1;
            o0.x = facc[mi][ni][0] * xs0 + bv.x;
            o0.y = facc[mi][ni][1] * xs0 + bv.y;
            o1.x = facc[mi][ni][2] * xs1 + bv.x;
            o1.y = facc[mi][ni][3] * xs1 + bv.y;
            *(float2*)(out + (size_t)row0 * O_DIM + col) = o0;
            *(float2*)(out + (size_t)row1 * O_DIM + col) = o1;
        }
    }
}

// ---------------------------------------------------------------------------
extern "C" void kernel_launch(void* const* d_in, const int* in_sizes, int n_in,
                              void* d_out, int out_size) {
    const float* x        = (const float*)d_in[0];
    const int*   qweight  = (const int*)d_in[1];
    const float* w_scales = (const float*)d_in[2];
    const int*   w_zp     = (const int*)d_in[3];
    const float* bias     = (const float*)d_in[4];
    float*       out      = (float*)d_out;

    quant_act_kernel<<<S_TOK, 256>>>(x);
    dequant_w_kernel<<<O_DIM, 256>>>(qweight, w_scales, w_zp);

    const int smem_bytes = 2 * STAGE_BYTES;   // 128KB
    cudaFuncSetAttribute(gemm_f16_kernel,
                         cudaFuncAttributeMaxDynamicSharedMemorySize, smem_bytes);
    const int grid = (S_TOK / BM) * (O_DIM / BN);   // 512
    gemm_f16_kernel<<<grid, THREADS, smem_bytes>>>(bias, out);
}

// round 4
// speedup vs baseline: 3.3231x; 2.0353x over previous
#include <cuda_runtime.h>
#include <cuda_fp16.h>
#include <cstdint>

// Problem shape (fixed)
#define S_TOK 2048
#define K_DIM 4096
#define O_DIM 4096
#define NGRP  32

// GEMM tiling
#define BM 128
#define BN 256
#define BK 64
#define NKT (K_DIM / BK)     // 64
#define THREADS 256          // 8 warps: 2 (M) x 4 (N), warp tile 64x64
#define NSTAGE 3

// Device-global scratch (no runtime allocation allowed)
__device__ __align__(128) __half g_xq[(size_t)S_TOK * K_DIM];   // centered quantized activations
__device__ float  g_xscale[S_TOK];
__device__ __align__(128) __half g_wq[(size_t)O_DIM * K_DIM];   // dequantized weights (code-zp)*scale

// ---------------------------------------------------------------------------
// Kernel 1: per-token asymmetric activation quantization -> centered fp16
// ---------------------------------------------------------------------------
__global__ __launch_bounds__(256) void quant_act_kernel(const float* __restrict__ x) {
    const int row = blockIdx.x;
    const int tid = threadIdx.x;
    const float* xr = x + (size_t)row * K_DIM;

    float4 v[4];
    float mn = INFINITY, mx = -INFINITY;
#pragma unroll
    for (int i = 0; i < 4; i++) {
        v[i] = ((const float4*)xr)[tid + i * 256];
        mn = fminf(mn, fminf(fminf(v[i].x, v[i].y), fminf(v[i].z, v[i].w)));
        mx = fmaxf(mx, fmaxf(fmaxf(v[i].x, v[i].y), fmaxf(v[i].z, v[i].w)));
    }
#pragma unroll
    for (int o = 16; o; o >>= 1) {
        mn = fminf(mn, __shfl_xor_sync(0xffffffffu, mn, o));
        mx = fmaxf(mx, __shfl_xor_sync(0xffffffffu, mx, o));
    }
    __shared__ float smn[8], smx[8];
    __shared__ float s_scale, s_zp;
    const int wid = tid >> 5, lane = tid & 31;
    if (lane == 0) { smn[wid] = mn; smx[wid] = mx; }
    __syncthreads();
    if (tid == 0) {
        float a = smn[0], b = smx[0];
#pragma unroll
        for (int i = 1; i < 8; i++) { a = fminf(a, smn[i]); b = fmaxf(b, smx[i]); }
        float sc = fmaxf((b - a) * (1.0f / 255.0f), 1e-5f);
        float zp = fminf(fmaxf(rintf(-a / sc), 0.0f), 255.0f);
        s_scale = sc; s_zp = zp;
        g_xscale[row] = sc;
    }
    __syncthreads();
    const float sc = s_scale, zp = s_zp;

    __half* outp = g_xq + (size_t)row * K_DIM;
#pragma unroll
    for (int i = 0; i < 4; i++) {
        float q0 = fminf(fmaxf(rintf(v[i].x / sc) + zp, 0.0f), 255.0f) - zp;
        float q1 = fminf(fmaxf(rintf(v[i].y / sc) + zp, 0.0f), 255.0f) - zp;
        float q2 = fminf(fmaxf(rintf(v[i].z / sc) + zp, 0.0f), 255.0f) - zp;
        float q3 = fminf(fmaxf(rintf(v[i].w / sc) + zp, 0.0f), 255.0f) - zp;
        __half2 p0, p1;
        p0.x = __float2half_rn(q0); p0.y = __float2half_rn(q1);
        p1.x = __float2half_rn(q2); p1.y = __float2half_rn(q3);
        ((__half2*)outp)[(tid + i * 256) * 2 + 0] = p0;
        ((__half2*)outp)[(tid + i * 256) * 2 + 1] = p1;
    }
}

// ---------------------------------------------------------------------------
// Kernel 2: weight dequant int32 codes -> fp16 (code - zp) * scale
// ---------------------------------------------------------------------------
__global__ __launch_bounds__(256) void dequant_w_kernel(
    const int* __restrict__ qw, const float* __restrict__ wsc, const int* __restrict__ wzp)
{
    const int o = blockIdx.x;
    const int t = threadIdx.x;
    const int g = t >> 3;
    const float s = wsc[o * NGRP + g];
    const float z = (float)wzp[o * NGRP + g];
    const int4* src = (const int4*)(qw + (size_t)o * K_DIM + t * 16);
    __half2 h[8];
#pragma unroll
    for (int j = 0; j < 4; j++) {
        int4 c = src[j];
        h[j * 2 + 0].x = __float2half_rn(((float)c.x - z) * s);
        h[j * 2 + 0].y = __float2half_rn(((float)c.y - z) * s);
        h[j * 2 + 1].x = __float2half_rn(((float)c.z - z) * s);
        h[j * 2 + 1].y = __float2half_rn(((float)c.w - z) * s);
    }
    uint4* dst = (uint4*)(g_wq + (size_t)o * K_DIM + t * 16);
    dst[0] = *(uint4*)&h[0];
    dst[1] = *(uint4*)&h[4];
}

// ---------------------------------------------------------------------------
// Kernel 3: fp16 GEMM, 128x256 CTA tile, 64x64 warp tile, 3-stage cp.async
// ---------------------------------------------------------------------------
#define MMA16816(d, a0, a1, a2, a3, b0, b1)                                        \
    asm volatile(                                                                  \
        "mma.sync.aligned.m16n8k16.row.col.f32.f16.f16.f32 "                       \
        "{%0,%1,%2,%3},{%4,%5,%6,%7},{%8,%9},{%0,%1,%2,%3};"                       \
        : "+f"(d[0]), "+f"(d[1]), "+f"(d[2]), "+f"(d[3])                           \
        : "r"(a0), "r"(a1), "r"(a2), "r"(a3), "r"(b0), "r"(b1))

__device__ __forceinline__ void cp_async16(uint32_t saddr, const void* g) {
    asm volatile("cp.async.cg.shared.global [%0], [%1], 16;" :: "r"(saddr), "l"(g));
}
#define CP_COMMIT() asm volatile("cp.async.commit_group;")

// per-tile: rows of 64 fp16 = 128B; chunk c (16B) swizzled by row
__device__ __forceinline__ uint32_t sw(int r, int c) {
    return (uint32_t)(r * 128 + ((c ^ (r & 7)) << 4));
}

#define A_BYTES (BM * 128)                   // 16384
#define B_BYTES (BN * 128)                   // 32768
#define STAGE_BYTES (A_BYTES + B_BYTES)      // 49152
#define GEMM_SMEM (NSTAGE * STAGE_BYTES)     // 147456

extern __shared__ char smem_raw[];

__global__ __launch_bounds__(THREADS, 1) void gemm_f16_kernel(
    const float* __restrict__ bias, float* __restrict__ out)
{
    const int tid  = threadIdx.x;
    const int warp = tid >> 5, lane = tid & 31;
    const int warp_m = warp & 1;   // 2 along M (64 rows)
    const int warp_n = warp >> 1;  // 4 along N (64 cols)
    const int bm = (blockIdx.x & 15) * BM;       // m fastest -> weight L2 reuse
    const int bn = (blockIdx.x >> 4) * BN;

    const uint32_t sbase = (uint32_t)__cvta_generic_to_shared(smem_raw);

    const __half* gA = g_xq + (size_t)bm * K_DIM;
    const __half* gB = g_wq + (size_t)bn * K_DIM;

    auto load_stage = [&](int s, int kt) {
        const uint32_t a_s = sbase + s * STAGE_BYTES;
        const uint32_t b_s = a_s + A_BYTES;
        const size_t koff = (size_t)kt * BK;
#pragma unroll
        for (int i = 0; i < 4; i++) {           // A: 1024 chunks
            const int ch = tid + i * 256;
            const int r = ch >> 3, c = ch & 7;
            cp_async16(a_s + sw(r, c), gA + (size_t)r * K_DIM + koff + c * 8);
        }
#pragma unroll
        for (int i = 0; i < 8; i++) {           // B: 2048 chunks
            const int ch = tid + i * 256;
            const int r = ch >> 3, c = ch & 7;
            cp_async16(b_s + sw(r, c), gB + (size_t)r * K_DIM + koff + c * 8);
        }
        CP_COMMIT();
    };

    float acc[4][8][4];
#pragma unroll
    for (int i = 0; i < 4; i++)
#pragma unroll
        for (int j = 0; j < 8; j++)
#pragma unroll
            for (int k = 0; k < 4; k++) acc[i][j][k] = 0.f;

    load_stage(0, 0);
    load_stage(1, 1);

    for (int kt = 0; kt < NKT; kt++) {
        const int s = kt % NSTAGE;

        // issue prefetch for kt+2 into the free slot, then wait for stage kt
        if (kt + 2 < NKT) {
            load_stage((kt + 2) % NSTAGE, kt + 2);
            asm volatile("cp.async.wait_group 2;");
        } else if (kt + 1 < NKT) {
            asm volatile("cp.async.wait_group 1;");
        } else {
            asm volatile("cp.async.wait_group 0;");
        }
        __syncthreads();

        const uint32_t a_s = sbase + s * STAGE_BYTES;
        const uint32_t b_s = a_s + A_BYTES;

#pragma unroll
        for (int ks = 0; ks < 4; ks++) {        // 4 k16 steps in BK=64
            uint32_t af[4][4], bf[4][4];
            // A: rows warp_m*64 + mi*16 + (lane&15), chunk ks*2 + (lane>>4)
            const int arow = warp_m * 64 + (lane & 15);
            const int ac   = ks * 2 + (lane >> 4);
#pragma unroll
            for (int mi = 0; mi < 4; mi++) {
                uint32_t addr = a_s + sw(arow + mi * 16, ac);
                asm volatile("ldmatrix.sync.aligned.m8n8.x4.shared.b16 {%0,%1,%2,%3},[%4];"
                             : "=r"(af[mi][0]), "=r"(af[mi][1]),
                               "=r"(af[mi][2]), "=r"(af[mi][3])
                             : "r"(addr));
            }
            // B: 4 x4 loads, each covers n16 x k16
            const int brow = warp_n * 64 + (lane >> 4) * 8 + (lane & 7);
            const int bc   = ks * 2 + ((lane >> 3) & 1);
#pragma unroll
            for (int nj = 0; nj < 4; nj++) {
                uint32_t addr = b_s + sw(brow + nj * 16, bc);
                asm volatile("ldmatrix.sync.aligned.m8n8.x4.shared.b16 {%0,%1,%2,%3},[%4];"
                             : "=r"(bf[nj][0]), "=r"(bf[nj][1]),
                               "=r"(bf[nj][2]), "=r"(bf[nj][3])
                             : "r"(addr));
            }
#pragma unroll
            for (int mi = 0; mi < 4; mi++)
#pragma unroll
                for (int nj = 0; nj < 4; nj++) {
                    MMA16816(acc[mi][nj * 2 + 0],
                             af[mi][0], af[mi][1], af[mi][2], af[mi][3],
                             bf[nj][0], bf[nj][1]);
                    MMA16816(acc[mi][nj * 2 + 1],
                             af[mi][0], af[mi][1], af[mi][2], af[mi][3],
                             bf[nj][2], bf[nj][3]);
                }
        }
        __syncthreads();   // all warps done with stage s before it is refilled
    }

    // epilogue: out = acc * x_scale[row] + bias[col]
#pragma unroll
    for (int mi = 0; mi < 4; mi++) {
        const int row0 = bm + warp_m * 64 + mi * 16 + (lane >> 2);
        const int row1 = row0 + 8;
        const float xs0 = g_xscale[row0];
        const float xs1 = g_xscale[row1];
        float* p0 = out + (size_t)row0 * O_DIM + bn;
        float* p1 = out + (size_t)row1 * O_DIM + bn;
#pragma unroll
        for (int nj = 0; nj < 8; nj++) {
            const int col = warp_n * 64 + nj * 8 + (lane & 3) * 2;
            const float2 bv = *(const float2*)(bias + bn + col);
            float2 o0, o1;
            o0.x = acc[mi][nj][0] * xs0 + bv.x;
            o0.y = acc[mi][nj][1] * xs0 + bv.y;
            o1.x = acc[mi][nj][2] * xs1 + bv.x;
            o1.y = acc[mi][nj][3] * xs1 + bv.y;
            *(float2*)(p0 + col) = o0;
            *(float2*)(p1 + col) = o1;
        }
    }
}

// ---------------------------------------------------------------------------
extern "C" void kernel_launch(void* const* d_in, const int* in_sizes, int n_in,
                              void* d_out, int out_size) {
    const float* x        = (const float*)d_in[0];
    const int*   qweight  = (const int*)d_in[1];
    const float* w_scales = (const float*)d_in[2];
    const int*   w_zp     = (const int*)d_in[3];
    const float* bias     = (const float*)d_in[4];
    float*       out      = (float*)d_out;

    quant_act_kernel<<<S_TOK, 256>>>(x);
    dequant_w_kernel<<<O_DIM, 256>>>(qweight, w_scales, w_zp);

    cudaFuncSetAttribute(gemm_f16_kernel,
                         cudaFuncAttributeMaxDynamicSharedMemorySize, GEMM_SMEM);
    const int grid = (S_TOK / BM) * (O_DIM / BN);   // 16 x 16 = 256
    gemm_f16_kernel<<<grid, THREADS, GEMM_SMEM>>>(bias, out);
}